// round 10
// baseline (speedup 1.0000x reference)
#include <cuda_runtime.h>
#include <cstdint>
#include <math.h>

// ---------------- problem constants ----------------
#define PDIM   128              // n_proxy_sets
#define EDIM   32               // elements per proxy set
#define DDIM   64               // feature dim
#define PE     (PDIM*EDIM)      // 4096 flattened proxies
#define NCH_CTA 32              // chunks per CTA (64 proxies each; 2 CTAs/segment)
#define TILE_M 128              // x rows per tile
#define THREADS 256
#define MAXB   1024
#define XQPITCH 80              // s8 row pitch (64 data + 16 pad, conflict-free LDS)

// W quantized to s8, pre-shuffled into per-thread mma-fragment order.
// uint4 index = (set*4 + n)*32 + lane ; set 0..127, n = 8-col block 0..3.
// uint4 = {b0(k0..15), b1(k16..31), b0(k32..47), b1(k48..63)} for that lane.
__device__ uint4 g_wq[PDIM * 4 * 32];        // 256 KB (L2-hot)
__device__ float g_wscale[PDIM];             // per-set dequant scale
__device__ int g_segoff[MAXB];

__device__ __forceinline__ int imax(int a, int b) { return a > b ? a : b; }

// ---------------- prep kernel: per-set quantize + fragment shuffle + scan ----------------
__global__ void prep_kernel(const float* __restrict__ w,
                            const int* __restrict__ index, int B) {
    if (blockIdx.x < PDIM) {
        __shared__ float wsm[EDIM * DDIM];   // 8 KB: this set's 32x64 weights
        __shared__ float wred[8];
        __shared__ float s_inv;
        const int s = blockIdx.x;
        const int t = threadIdx.x;
        const int lane = t & 31, warp = t >> 5;
        const float* wp = w + (size_t)s * (EDIM * DDIM);
        float am = 0.f;
        #pragma unroll
        for (int j = 0; j < 8; ++j) {
            float v = __ldg(wp + t + 256 * j);
            wsm[t + 256 * j] = v;
            am = fmaxf(am, fabsf(v));
        }
        #pragma unroll
        for (int o = 16; o > 0; o >>= 1)
            am = fmaxf(am, __shfl_xor_sync(0xffffffffu, am, o));
        if (lane == 0) wred[warp] = am;
        __syncthreads();
        if (t == 0) {
            float m = wred[0];
            #pragma unroll
            for (int j = 1; j < 8; ++j) m = fmaxf(m, wred[j]);
            g_wscale[s] = m / 127.f;
            s_inv = (m > 0.f) ? 127.f / m : 0.f;
        }
        __syncthreads();
        if (t < 128) {
            float inv = s_inv;
            int n  = t >> 5;                 // 8-col block
            int ln = t & 31;
            int col = n * 8 + (ln >> 2);     // proxy-in-set 0..31
            int kq  = (ln & 3) * 4;
            const float* pr = wsm + col * DDIM;
            uint32_t wd[4];
            #pragma unroll
            for (int h = 0; h < 4; ++h) {    // k bases 0,16,32,48
                int k0 = h * 16 + kq;
                int q0 = __float2int_rn(pr[k0 + 0] * inv);
                int q1 = __float2int_rn(pr[k0 + 1] * inv);
                int q2 = __float2int_rn(pr[k0 + 2] * inv);
                int q3 = __float2int_rn(pr[k0 + 3] * inv);
                wd[h] = (q0 & 255) | ((q1 & 255) << 8) | ((q2 & 255) << 16)
                      | ((uint32_t)(q3 & 255) << 24);
            }
            uint4 pk; pk.x = wd[0]; pk.y = wd[1]; pk.z = wd[2]; pk.w = wd[3];
            g_wq[(s * 4 + n) * 32 + ln] = pk;
        }
    } else {
        __shared__ int s[256];
        int t = threadIdx.x;
        int v[4]; int base = t * 4;
        int acc = 0;
        #pragma unroll
        for (int j = 0; j < 4; ++j) {
            v[j] = acc;
            int e = base + j;
            acc += (e < B) ? index[e] : 0;
        }
        s[t] = acc;
        __syncthreads();
        for (int o = 1; o < 256; o <<= 1) {
            int add = (t >= o) ? s[t - o] : 0;
            __syncthreads();
            s[t] += add;
            __syncthreads();
        }
        int pre = (t > 0) ? s[t - 1] : 0;
        #pragma unroll
        for (int j = 0; j < 4; ++j) {
            int e = base + j;
            if (e < B) g_segoff[e] = pre + v[j];
        }
    }
}

// ---------------- MMA primitive ----------------
__device__ __forceinline__ void mma_s8(int* c, const uint32_t* a,
                                       uint32_t b0, uint32_t b1) {
    asm volatile(
        "mma.sync.aligned.m16n8k32.row.col.s32.s8.s8.s32 "
        "{%0,%1,%2,%3}, {%4,%5,%6,%7}, {%8,%9}, {%0,%1,%2,%3};"
        : "+r"(c[0]), "+r"(c[1]), "+r"(c[2]), "+r"(c[3])
        : "r"(a[0]), "r"(a[1]), "r"(a[2]), "r"(a[3]), "r"(b0), "r"(b1));
}

#define LOAD4(dst, ptr) do {                     \
    (dst)[0] = __ldg((ptr));                     \
    (dst)[1] = __ldg((ptr) + 32);                \
    (dst)[2] = __ldg((ptr) + 64);                \
    (dst)[3] = __ldg((ptr) + 96); } while (0)

// ---------------- main kernel ----------------
// 2 CTAs per segment; each sweeps 32 proxy chunks (64 proxies = 2 sets each).
// 8 warps = 4 rgrp x 2 pg; warp tile 32 rows x 32 cols (= ONE proxy set) so
// max-over-elements happens in INTEGER domain (per-set w scale), dequant only
// touches the 4 surviving row-maxes. x quantized per-row to s8 in smem; B s8
// fragments streamed directly from L2 (no smem, no barriers in chunk loop).
__global__ __launch_bounds__(THREADS, 2)
void main_kernel(const float* __restrict__ x, const int* __restrict__ index,
                 float* __restrict__ out) {
    __shared__ char  xq[TILE_M * XQPITCH];   // 10 KB quantized x tile
    __shared__ float sxv[TILE_M];            // per-row x scales
    __shared__ float pooled2[64 * 32];       // 8 KB partials [p_local][slot]

    const int b    = blockIdx.x >> 1;
    const int half = blockIdx.x & 1;
    const int tid  = threadIdx.x;
    const int lane = tid & 31;
    const int warp = tid >> 5;
    const int rgrp = warp & 3;     // row-group (32 rows)
    const int pg   = warp >> 2;    // set within chunk (0/1)

    for (int i = tid; i < 64 * 32; i += THREADS) pooled2[i] = 0.f;

    const int off = g_segoff[b];
    const int len = index[b];

    // this warp's B fragment stream: set = half*64 + c*2 + pg
    const uint4* wf  = g_wq + ((size_t)(half * 64 + pg)) * 128 + lane;
    const float* gsw = g_wscale + half * 64 + pg;

    for (int tile = 0; tile * TILE_M < len; ++tile) {
        __syncthreads();   // pooled2 init / previous tile xq drain
        // ---- stage x tile: quantize per row to s8 (zero-pad ragged tail) ----
        {
            int row  = tid >> 1;
            int hh   = tid & 1;
            int rrem = len - tile * TILE_M;
            bool valid = row < rrem;
            const float4* xr = (const float4*)
                (x + ((size_t)(off + tile * TILE_M + row)) * DDIM + hh * 32);
            float4 v4[8];
            float am = 0.f;
            #pragma unroll
            for (int j = 0; j < 8; ++j) {
                float4 v = valid ? __ldg(xr + j) : make_float4(0.f, 0.f, 0.f, 0.f);
                v4[j] = v;
                am = fmaxf(am, fmaxf(fmaxf(fabsf(v.x), fabsf(v.y)),
                                     fmaxf(fabsf(v.z), fabsf(v.w))));
            }
            am = fmaxf(am, __shfl_xor_sync(0xffffffffu, am, 1));  // row pair
            float inv = (am > 0.f) ? 127.f / am : 0.f;
            if (hh == 0) sxv[row] = am / 127.f;
            uint32_t wd[8];
            #pragma unroll
            for (int j = 0; j < 8; ++j) {
                int q0 = __float2int_rn(v4[j].x * inv);
                int q1 = __float2int_rn(v4[j].y * inv);
                int q2 = __float2int_rn(v4[j].z * inv);
                int q3 = __float2int_rn(v4[j].w * inv);
                wd[j] = (q0 & 255) | ((q1 & 255) << 8) | ((q2 & 255) << 16)
                      | ((uint32_t)(q3 & 255) << 24);
            }
            uint4* dst = (uint4*)(xq + row * XQPITCH + hh * 32);
            uint4 p0; p0.x = wd[0]; p0.y = wd[1]; p0.z = wd[2]; p0.w = wd[3];
            uint4 p1; p1.x = wd[4]; p1.y = wd[5]; p1.z = wd[6]; p1.w = wd[7];
            dst[0] = p0; dst[1] = p1;
        }
        __syncthreads();   // xq, sxv visible

        // ---- A fragments (s8, m16n8k32 layout) + row scales, pinned ----
        uint32_t afr[2][2][4];
        float sxf[4];
        {
            int g = lane >> 2, tq = (lane & 3) * 4;
            #pragma unroll
            for (int m = 0; m < 2; ++m)
                #pragma unroll
                for (int k = 0; k < 2; ++k) {
                    const char* p0 = xq + (rgrp * 32 + m * 16 + g) * XQPITCH + k * 32 + tq;
                    afr[m][k][0] = *(const uint32_t*)(p0);
                    afr[m][k][1] = *(const uint32_t*)(p0 + 8 * XQPITCH);
                    afr[m][k][2] = *(const uint32_t*)(p0 + 16);
                    afr[m][k][3] = *(const uint32_t*)(p0 + 8 * XQPITCH + 16);
                }
            #pragma unroll
            for (int r = 0; r < 4; ++r) sxf[r] = sxv[rgrp * 32 + r * 8 + g];
        }

        // ---- barrier-free chunk sweep, double-buffered B fragments ----
        uint4 bufA[4], bufB[4];
        LOAD4(bufA, wf);
        float swA = __ldg(gsw), swB;
        for (int c = 0; c < NCH_CTA; c += 2) {
            LOAD4(bufB, wf + (c + 1) * 256);
            swB = __ldg(gsw + (c + 1) * 2);
            #pragma unroll
            for (int e = 0; e < 2; ++e) {           // e=0 -> chunk c, e=1 -> c+1
                const uint4* bb = e ? bufB : bufA;
                float sw = e ? swB : swA;
                int cc = c + e;

                int acc[2][4][4];
                #pragma unroll
                for (int m = 0; m < 2; ++m)
                    #pragma unroll
                    for (int n = 0; n < 4; ++n)
                        acc[m][n][0] = acc[m][n][1] = acc[m][n][2] = acc[m][n][3] = 0;
                #pragma unroll
                for (int k = 0; k < 2; ++k)
                    #pragma unroll
                    for (int n = 0; n < 4; ++n) {
                        uint32_t b0 = k ? bb[n].z : bb[n].x;
                        uint32_t b1 = k ? bb[n].w : bb[n].y;
                        mma_s8(acc[0][n], afr[0][k], b0, b1);
                        mma_s8(acc[1][n], afr[1][k], b0, b1);
                    }

                // integer max over this set's 32 cols (per-set scale: legal)
                int rm0 = imax(imax(imax(acc[0][0][0], acc[0][0][1]),
                                    imax(acc[0][1][0], acc[0][1][1])),
                               imax(imax(acc[0][2][0], acc[0][2][1]),
                                    imax(acc[0][3][0], acc[0][3][1])));
                int rm1 = imax(imax(imax(acc[0][0][2], acc[0][0][3]),
                                    imax(acc[0][1][2], acc[0][1][3])),
                               imax(imax(acc[0][2][2], acc[0][2][3]),
                                    imax(acc[0][3][2], acc[0][3][3])));
                int rm2 = imax(imax(imax(acc[1][0][0], acc[1][0][1]),
                                    imax(acc[1][1][0], acc[1][1][1])),
                               imax(imax(acc[1][2][0], acc[1][2][1]),
                                    imax(acc[1][3][0], acc[1][3][1])));
                int rm3 = imax(imax(imax(acc[1][0][2], acc[1][0][3]),
                                    imax(acc[1][1][2], acc[1][1][3])),
                               imax(imax(acc[1][2][2], acc[1][2][3]),
                                    imax(acc[1][3][2], acc[1][3][3])));
                rm0 = imax(rm0, __shfl_xor_sync(0xffffffffu, rm0, 1));
                rm1 = imax(rm1, __shfl_xor_sync(0xffffffffu, rm1, 1));
                rm2 = imax(rm2, __shfl_xor_sync(0xffffffffu, rm2, 1));
                rm3 = imax(rm3, __shfl_xor_sync(0xffffffffu, rm3, 1));
                rm0 = imax(rm0, __shfl_xor_sync(0xffffffffu, rm0, 2));
                rm1 = imax(rm1, __shfl_xor_sync(0xffffffffu, rm1, 2));
                rm2 = imax(rm2, __shfl_xor_sync(0xffffffffu, rm2, 2));
                rm3 = imax(rm3, __shfl_xor_sync(0xffffffffu, rm3, 2));

                // dequant only the 4 row-maxes: t = rm * sx_row * sw_set
                float s4 = (__int2float_rn(rm0) * sxf[0]
                          + __int2float_rn(rm1) * sxf[1])
                         + (__int2float_rn(rm2) * sxf[2]
                          + __int2float_rn(rm3) * sxf[3]);
                s4 *= sw;
                if ((lane & 3) == 0)
                    pooled2[(cc * 2 + pg) * 32 + rgrp * 8 + (lane >> 2)] += s4;
            }
            if (c + 2 < NCH_CTA) {
                LOAD4(bufA, wf + (c + 2) * 256);
                swA = __ldg(gsw + (c + 2) * 2);
            }
        }
    }

    // ---- CTA-end reduction: 64 p x 32 slots -> out (unnormalized) ----
    __syncthreads();
    {
        int pl = tid >> 2, q = tid & 3;
        const float* row = &pooled2[pl * 32 + q * 8];
        float s = 0.f;
        #pragma unroll
        for (int j = 0; j < 8; ++j) s += row[j];
        s += __shfl_xor_sync(0xffffffffu, s, 1);
        s += __shfl_xor_sync(0xffffffffu, s, 2);
        if (q == 0) out[(size_t)b * PDIM + half * 64 + pl] = s;
    }
}

// ---------------- normalize kernel ----------------
__global__ void norm_kernel(float* __restrict__ out) {
    __shared__ float red[4];
    int b = blockIdx.x, t = threadIdx.x;   // 128 threads
    float v = out[(size_t)b * PDIM + t];
    float s2 = v * v;
    #pragma unroll
    for (int o = 16; o > 0; o >>= 1) s2 += __shfl_xor_sync(0xffffffffu, s2, o);
    if ((t & 31) == 0) red[t >> 5] = s2;
    __syncthreads();
    float nrm = sqrtf(red[0] + red[1] + red[2] + red[3]);
    out[(size_t)b * PDIM + t] = v / fmaxf(nrm, 1e-12f);
}

// ---------------- launch ----------------
extern "C" void kernel_launch(void* const* d_in, const int* in_sizes, int n_in,
                              void* d_out, int out_size) {
    const float* x     = (const float*)d_in[0];
    const float* w     = (const float*)d_in[1];
    const int*   index = (const int*)d_in[2];
    float* out = (float*)d_out;

    int B = in_sizes[2];             // 1024

    prep_kernel<<<129, 256>>>(w, index, B);
    main_kernel<<<2 * B, THREADS>>>(x, index, out);
    norm_kernel<<<B, 128>>>(out);
}

// round 11
// speedup vs baseline: 2.5501x; 2.5501x over previous
#include <cuda_runtime.h>
#include <cuda_bf16.h>
#include <cstdint>
#include <math.h>

// ---------------- problem constants ----------------
#define PDIM   128              // n_proxy_sets
#define EDIM   32               // elements per proxy set
#define DDIM   64               // feature dim
#define PE     (PDIM*EDIM)      // 4096 flattened proxies
#define NCH_CTA 32              // chunks per CTA (64 proxies each; 2 CTAs/segment)
#define TILE_M 128              // x rows per tile
#define XPITCH 72               // padded bf16 row pitch (conflict-free ldsm)
#define THREADS 256
#define MAXB   1024

// W pre-shuffled into per-thread mma-fragment order:
// uint4 index = ((cpg)*8 + f)*32 + lane,  cpg = chunk*2+pg (0..127), f = nl*2+half
// uint4 = {b0(k16=2h), b1(k16=2h), b0(k16=2h+1), b1(k16=2h+1)} for (lane,nl)
__device__ uint4 g_wfrag[PE * DDIM / 8];     // 512 KB (L2-hot)
__device__ int g_segoff[MAXB];

// ---------------- prep kernel: fragment-shuffle conversion + scan ----------------
__global__ void prep_kernel(const float* __restrict__ w,
                            const int* __restrict__ index, int B) {
    if (blockIdx.x < 128) {
        int id   = blockIdx.x * 256 + threadIdx.x;   // 0..32767 uint4s
        int lane = id & 31;
        int f    = (id >> 5) & 7;
        int cpg  = id >> 8;                          // 0..127
        int nl   = f >> 1, half = f & 1;
        int g    = lane >> 2, t = lane & 3;
        const float* wr = w + ((size_t)(cpg * 32 + nl * 8 + g)) * DDIM;
        int ka = half * 32;                          // k16=(2*half)*16
        __nv_bfloat162 x = __floats2bfloat162_rn(wr[ka +      t*2], wr[ka +      t*2 + 1]);
        __nv_bfloat162 y = __floats2bfloat162_rn(wr[ka +  8 + t*2], wr[ka +  8 + t*2 + 1]);
        __nv_bfloat162 z = __floats2bfloat162_rn(wr[ka + 16 + t*2], wr[ka + 16 + t*2 + 1]);
        __nv_bfloat162 u = __floats2bfloat162_rn(wr[ka + 24 + t*2], wr[ka + 24 + t*2 + 1]);
        uint4 pk;
        pk.x = *(uint32_t*)&x; pk.y = *(uint32_t*)&y;
        pk.z = *(uint32_t*)&z; pk.w = *(uint32_t*)&u;
        g_wfrag[id] = pk;
    } else {
        __shared__ int s[256];
        int t = threadIdx.x;
        int v[4]; int base = t * 4;
        int acc = 0;
        #pragma unroll
        for (int j = 0; j < 4; ++j) {
            v[j] = acc;
            int e = base + j;
            acc += (e < B) ? index[e] : 0;
        }
        s[t] = acc;
        __syncthreads();
        for (int o = 1; o < 256; o <<= 1) {
            int add = (t >= o) ? s[t - o] : 0;
            __syncthreads();
            s[t] += add;
            __syncthreads();
        }
        int pre = (t > 0) ? s[t - 1] : 0;
        #pragma unroll
        for (int j = 0; j < 4; ++j) {
            int e = base + j;
            if (e < B) g_segoff[e] = pre + v[j];
        }
    }
}

// ---------------- MMA primitives ----------------
__device__ __forceinline__ void ldsm_x4(uint32_t& r0, uint32_t& r1,
                                        uint32_t& r2, uint32_t& r3,
                                        const void* p) {
    uint32_t a = (uint32_t)__cvta_generic_to_shared(p);
    asm volatile("ldmatrix.sync.aligned.m8n8.x4.shared.b16 {%0,%1,%2,%3}, [%4];"
                 : "=r"(r0), "=r"(r1), "=r"(r2), "=r"(r3) : "r"(a));
}

__device__ __forceinline__ void mma_bf16(float* c, const uint32_t* a,
                                         uint32_t b0, uint32_t b1) {
    asm volatile(
        "mma.sync.aligned.m16n8k16.row.col.f32.bf16.bf16.f32 "
        "{%0,%1,%2,%3}, {%4,%5,%6,%7}, {%8,%9}, {%0,%1,%2,%3};"
        : "+f"(c[0]), "+f"(c[1]), "+f"(c[2]), "+f"(c[3])
        : "r"(a[0]), "r"(a[1]), "r"(a[2]), "r"(a[3]), "r"(b0), "r"(b1));
}

// one 16-col stage: 16 HMMAs from fragment-direct B regs, fold into rm
__device__ __forceinline__ void stage_compute(const uint4* bb,
                                              const uint32_t afr[2][4][4],
                                              float rm[4], bool first) {
    float acc[2][2][4];
    #pragma unroll
    for (int m = 0; m < 2; ++m)
        #pragma unroll
        for (int nlh = 0; nlh < 2; ++nlh)
            acc[m][nlh][0] = acc[m][nlh][1] = acc[m][nlh][2] = acc[m][nlh][3] = 0.f;

    #pragma unroll
    for (int k16 = 0; k16 < 4; ++k16) {
        #pragma unroll
        for (int nlh = 0; nlh < 2; ++nlh) {
            uint4 v = bb[nlh * 2 + (k16 >> 1)];
            uint32_t b0 = (k16 & 1) ? v.z : v.x;
            uint32_t b1 = (k16 & 1) ? v.w : v.y;
            mma_bf16(acc[0][nlh], afr[0][k16], b0, b1);
            mma_bf16(acc[1][nlh], afr[1][k16], b0, b1);
        }
    }
    #pragma unroll
    for (int m = 0; m < 2; ++m) {
        float lo = fmaxf(fmaxf(acc[m][0][0], acc[m][0][1]),
                         fmaxf(acc[m][1][0], acc[m][1][1]));
        float hi = fmaxf(fmaxf(acc[m][0][2], acc[m][0][3]),
                         fmaxf(acc[m][1][2], acc[m][1][3]));
        if (first) { rm[m * 2] = lo; rm[m * 2 + 1] = hi; }
        else       { rm[m * 2] = fmaxf(rm[m * 2], lo);
                     rm[m * 2 + 1] = fmaxf(rm[m * 2 + 1], hi); }
    }
}

#define LOAD4(dst, ptr) do {                     \
    (dst)[0] = __ldg((ptr));                     \
    (dst)[1] = __ldg((ptr) + 32);                \
    (dst)[2] = __ldg((ptr) + 64);                \
    (dst)[3] = __ldg((ptr) + 96); } while (0)

// ---------------- main kernel ----------------
// 2 CTAs per segment; each sweeps 32 proxy chunks. 8 warps = 4 rgrp x 2 pg.
// B fragments read DIRECTLY from g_wfrag via coalesced LDG.128 (no smem, no
// barriers in chunk loop), 2-stage register pipeline. Chunk reductions are
// DEFERRED one chunk: chunk c's shuffle-max chain executes after chunk c+1's
// first 16 HMMAs issue, so it overlaps tensor work instead of stalling on it.
__global__ __launch_bounds__(THREADS, 2)
void main_kernel(const float* __restrict__ x, const int* __restrict__ index,
                 float* __restrict__ out) {
    __shared__ __nv_bfloat16 xs[TILE_M * XPITCH];   // 18 KB
    __shared__ float pooled2[64 * 32];              // 8 KB [p_local][slot]

    const int b    = blockIdx.x >> 1;
    const int half = blockIdx.x & 1;
    const int tid  = threadIdx.x;
    const int lane = tid & 31;
    const int warp = tid >> 5;
    const int rgrp = warp & 3;     // row-group (32 rows)
    const int pg   = warp >> 2;    // proxy-group within chunk (0/1)

    for (int i = tid; i < 64 * 32; i += THREADS) pooled2[i] = 0.f;

    const int off = g_segoff[b];
    const int len = index[b];

    // this warp's fragment stream: half selects 32-chunk range; chunk stride 512 u4
    const uint4* wf = g_wfrag + (size_t)half * 16384 + pg * 256 + lane;

    for (int tile = 0; tile * TILE_M < len; ++tile) {
        __syncthreads();   // pooled2 init / previous tile xs drain

        // ---- prefetch chunk 0 stage 0 EARLY (hides L2 miss under staging) ----
        uint4 bufA[4], bufB[4];
        LOAD4(bufA, wf);

        // ---- stage x tile to bf16 smem (zero-pad ragged tail) ----
        {
            int row  = tid >> 1;
            int hh   = tid & 1;
            int rrem = len - tile * TILE_M;
            bool valid = row < rrem;
            const float* xr = x + ((size_t)(off + tile * TILE_M + row)) * DDIM + hh * 32;
            __nv_bfloat162* dst = (__nv_bfloat162*)&xs[row * XPITCH + hh * 32];
            #pragma unroll
            for (int j = 0; j < 8; ++j) {
                float4 v = valid ? __ldg((const float4*)xr + j)
                                 : make_float4(0.f, 0.f, 0.f, 0.f);
                dst[2 * j]     = __floats2bfloat162_rn(v.x, v.y);
                dst[2 * j + 1] = __floats2bfloat162_rn(v.z, v.w);
            }
        }
        __syncthreads();   // xs visible

        // ---- A fragments: 32 rows per warp, pinned across all chunks ----
        uint32_t afr[2][4][4];
        #pragma unroll
        for (int m = 0; m < 2; ++m) {
            const __nv_bfloat16* base =
                &xs[(rgrp * 32 + m * 16 + (lane & 15)) * XPITCH + (lane >> 4) * 8];
            #pragma unroll
            for (int k = 0; k < 4; ++k)
                ldsm_x4(afr[m][k][0], afr[m][k][1], afr[m][k][2], afr[m][k][3],
                        base + k * 16);
        }

        // ---- barrier-free chunk sweep; reduction deferred one chunk ----
        float rmP[4];
        #pragma unroll 1
        for (int c = 0; c < NCH_CTA; ++c) {
            const uint4* cbase = wf + c * 512;
            // prefetch stage 1 of chunk c, then compute stage 0
            LOAD4(bufB, cbase + 128);
            float rm[4];
            stage_compute(bufA, afr, rm, true);

            // deferred reduction of chunk c-1 (rmP long ready; overlaps HMMAs)
            if (c > 0) {
                #pragma unroll
                for (int r = 0; r < 4; ++r) {
                    rmP[r] = fmaxf(rmP[r], __shfl_xor_sync(0xffffffffu, rmP[r], 1));
                    rmP[r] = fmaxf(rmP[r], __shfl_xor_sync(0xffffffffu, rmP[r], 2));
                }
                float s4 = (rmP[0] + rmP[1]) + (rmP[2] + rmP[3]);
                if ((lane & 3) == 0)
                    pooled2[((c - 1) * 2 + pg) * 32 + rgrp * 8 + (lane >> 2)] += s4;
            }

            // prefetch stage 0 of chunk c+1, then compute stage 1
            if (c + 1 < NCH_CTA) LOAD4(bufA, cbase + 512);
            stage_compute(bufB, afr, rm, false);
            rmP[0] = rm[0]; rmP[1] = rm[1]; rmP[2] = rm[2]; rmP[3] = rm[3];
        }
        // final chunk's reduction
        {
            #pragma unroll
            for (int r = 0; r < 4; ++r) {
                rmP[r] = fmaxf(rmP[r], __shfl_xor_sync(0xffffffffu, rmP[r], 1));
                rmP[r] = fmaxf(rmP[r], __shfl_xor_sync(0xffffffffu, rmP[r], 2));
            }
            float s4 = (rmP[0] + rmP[1]) + (rmP[2] + rmP[3]);
            if ((lane & 3) == 0)
                pooled2[((NCH_CTA - 1) * 2 + pg) * 32 + rgrp * 8 + (lane >> 2)] += s4;
        }
    }

    // ---- CTA-end reduction: 64 p x 32 slots -> out (unnormalized) ----
    __syncthreads();
    {
        int pl = tid >> 2, q = tid & 3;
        const float* row = &pooled2[pl * 32 + q * 8];
        float s = 0.f;
        #pragma unroll
        for (int j = 0; j < 8; ++j) s += row[j];
        s += __shfl_xor_sync(0xffffffffu, s, 1);
        s += __shfl_xor_sync(0xffffffffu, s, 2);
        if (q == 0) out[(size_t)b * PDIM + half * 64 + pl] = s;
    }
}

// ---------------- normalize kernel ----------------
__global__ void norm_kernel(float* __restrict__ out) {
    __shared__ float red[4];
    int b = blockIdx.x, t = threadIdx.x;   // 128 threads
    float v = out[(size_t)b * PDIM + t];
    float s2 = v * v;
    #pragma unroll
    for (int o = 16; o > 0; o >>= 1) s2 += __shfl_xor_sync(0xffffffffu, s2, o);
    if ((t & 31) == 0) red[t >> 5] = s2;
    __syncthreads();
    float nrm = sqrtf(red[0] + red[1] + red[2] + red[3]);
    out[(size_t)b * PDIM + t] = v / fmaxf(nrm, 1e-12f);
}

// ---------------- launch ----------------
extern "C" void kernel_launch(void* const* d_in, const int* in_sizes, int n_in,
                              void* d_out, int out_size) {
    const float* x     = (const float*)d_in[0];
    const float* w     = (const float*)d_in[1];
    const int*   index = (const int*)d_in[2];
    float* out = (float*)d_out;

    int B = in_sizes[2];             // 1024

    prep_kernel<<<129, 256>>>(w, index, B);
    main_kernel<<<2 * B, THREADS>>>(x, index, out);
    norm_kernel<<<B, 128>>>(out);
}